// round 15
// baseline (speedup 1.0000x reference)
#include <cuda_runtime.h>

// StateSpaceDiffusionModel: y[b,h,:] = causal_conv(u[b,h,:], f[h,:])
// reduced exactly to a scalar order-64 IIR+FIR (transposed direct form II):
//   y_t = c0*u_t + S[1]
//   S[i] <- S[i+1] + A'[i]*y_t + C'[i]*u_t   (merged delay line, i=1..64)
// A'[i] = a_{i-1} (1<=i<=64), C'[i] = c_i (1<=i<=63).
//
// R14 = R6's redundant-head body (y computed locally in every lane; the only
// cross-lane datum is each lane's OLD tail pair T[0]) with BOTH shuffles
// replaced by warp-synchronous volatile-SMEM exchange:
//   - lane stores fresh T[0] at iteration end (STS.64, parity buffer)
//   - consumers read it NEXT iteration (LDS.64): leader's -> head base,
//     neighbor's -> tail boundary
// Same-warp in-order issue makes STS-before-LDS guaranteed; `volatile`
// prevents compiler reordering. ZERO WARPSYNC / SHFL / BAR in the hot loop,
// so ptxas can weave the whole 2-step body into one short schedule.

#define HH 512
#define NN 64
#define BB 16
#define LL 2048

__device__ float g_a[HH * NN];
__device__ float g_c[HH * NN];

// ---------------- Kernel 1: per-head coefficients (trivial) ----------------
__global__ void coef_kernel(const float* __restrict__ k) {
    __shared__ float sh[NN];
    __shared__ float shd[NN];
    __shared__ float shP[NN];
    __shared__ float shsum;
    int h = blockIdx.x;
    int j = threadIdx.x;
    float kv = k[h * NN + j];
    float kc = fminf(fmaxf(kv, 1.0f / 16.0f), 1.0f);
    sh[j] = kc;
    __syncthreads();
    if (j == 0) {
        float s = 0.f;
        for (int i = 0; i < NN; i++) s += sh[i];
        shsum = s;
    }
    __syncthreads();
    float kn = kc / shsum;                       // L1-normalized clamped k
    float s = (j < NN - 1) ? (1.0f + kn) : kn;   // column L1 norm of (A + b k^T)
    float w = kn / s;                            // M[0, j]
    shd[j] = 1.0f / s;                           // M[j+1, j] subdiagonal
    __syncthreads();
    if (j == 0) {
        float P = 1.f;
        for (int i = 0; i < NN; i++) { shP[i] = P; P *= shd[i]; }
    }
    __syncthreads();
    float Pj = shP[j];
    g_a[h * NN + j] = w * Pj;    // IIR taps
    g_c[h * NN + j] = kv * Pj;   // FIR taps (original k!)
}

// ---------------- packed f32x2 helpers ----------------
typedef unsigned long long ull;
__device__ __forceinline__ ull pack2(float lo, float hi) {
    ull r; asm("mov.b64 %0, {%1,%2};" : "=l"(r) : "f"(lo), "f"(hi)); return r;
}
__device__ __forceinline__ void unpack2(ull v, float& lo, float& hi) {
    asm("mov.b64 {%0,%1}, %2;" : "=f"(lo), "=f"(hi) : "l"(v));
}
__device__ __forceinline__ ull fma2(ull a, ull b, ull c) {
    ull d; asm("fma.rn.f32x2 %0, %1, %2, %3;" : "=l"(d) : "l"(a), "l"(b), "l"(c)); return d;
}

// ---------------- Kernel 2: redundant-head scan, fence-free exchange -------
// Warp = 4 sequences x 8 lanes (one warp per CTA). Per 2-step iteration:
//  head (ALL lanes, identical):
//   y0 = c0*u0 + S1 ; y1 = A'1*y0 + c0*u1 + C'1*u0 + S2
//   P12'' = P34_old + (A'2,A'3)y0d + (A'1,A'2)y1d + (C'2,C'3)u0d + (C'1,C'2)u1d
//   P34'' = bc56    + (A'4,A'5)y0d + (A'3,A'4)y1d + (C'4,C'5)u0d + (C'3,C'4)u1d
//   bc56 = (S5,S6)_old = leader lane's OLD tail pair 0 (smem, written last iter)
//  tail (lane r owns pairs p=0..3, base slot s = 8r+5+2p):
//   T''[p] = T_old[p+1] + Ae_p*y0d + Ao_p*y1d + Ce_p*u0d + Co_p*u1d
//   T_old[4] = next lane's OLD T[0] (smem; zero on r==7)
// Exchange is one STS.64 per lane per iteration + two LDS.64 reads next
// iteration; parity buffer index == `half` (compile-time static). No sync ops.
#define PD 2   // float4 FIFO slots; each slot feeds 2 iterations (4 timesteps)

__global__ void __launch_bounds__(32)
scan_kernel(const float* __restrict__ u, float* __restrict__ y) {
    __shared__ ull smx[2][33];     // [parity][lane] old T[0] exchange
    volatile ull (*smb)[33] = smx;

    int lane = threadIdx.x & 31;
    int g = lane >> 3;   // sequence within warp (0..3)
    int r = lane & 7;    // lane within group (0..7)
    int gl = lane & ~7;  // group leader
    int seq = blockIdx.x * 4 + g;     // 0..8191
    int h = seq & (HH - 1);
    const float4* ubase4 = (const float4*)(u + (size_t)seq * LL);
    ull* ybase2 = (ull*)(y + (size_t)seq * LL);

    const float* ah = g_a + h * NN;   // A'(i) = ah[i-1], valid i=1..64
    const float* ch = g_c + h * NN;   // C'(i) = ch[i],   valid i=1..63

    // ---- tail taps: base slot s = 8r+5+2p ----
    ull Ae[4], Ao[4], Ce[4], Co[4], T[4];
#pragma unroll
    for (int p = 0; p < 4; p++) {
        int s = 8 * r + 5 + 2 * p;
        float A0v = (s     <= 64) ? ah[s - 1] : 0.f;   // A'(s)
        float A1v = (s + 1 <= 64) ? ah[s]     : 0.f;   // A'(s+1)
        float A2v = (s + 2 <= 64) ? ah[s + 1] : 0.f;   // A'(s+2)
        float C0v = (s     <= 63) ? ch[s]     : 0.f;   // C'(s)
        float C1v = (s + 1 <= 63) ? ch[s + 1] : 0.f;
        float C2v = (s + 2 <= 63) ? ch[s + 2] : 0.f;
        Ae[p] = pack2(A1v, A2v);   // * y0d
        Ao[p] = pack2(A0v, A1v);   // * y1d
        Ce[p] = pack2(C1v, C2v);   // * u0d
        Co[p] = pack2(C0v, C1v);   // * u1d
        T[p] = 0ull;
    }

    // ---- head taps (all lanes identical) ----
    float A1h = ah[0], A2h = ah[1], A3h = ah[2], A4h = ah[3], A5h = ah[4];
    float c0h = ch[0], C1h = ch[1], C2h = ch[2], C3h = ch[3], C4h = ch[4], C5h = ch[5];
    ull HA12e = pack2(A2h, A3h);   // P12: * y0d
    ull HA12o = pack2(A1h, A2h);   //      * y1d
    ull HC12e = pack2(C2h, C3h);   //      * u0d
    ull HC12o = pack2(C1h, C2h);   //      * u1d
    ull HA34e = pack2(A4h, A5h);   // P34: * y0d
    ull HA34o = pack2(A3h, A4h);   //      * y1d
    ull HC34e = pack2(C4h, C5h);   //      * u0d
    ull HC34o = pack2(C3h, C4h);   //      * u1d
    ull P12 = 0ull, P34 = 0ull;
    float S1 = 0.f, S2 = 0.f;

    // prime exchange buffers (state starts at zero); single warp, in-order
    smb[0][lane] = 0ull;
    smb[1][lane] = 0ull;
    if (lane == 0) { smb[0][32] = 0ull; smb[1][32] = 0ull; }
    __syncthreads();   // one-time, outside the loop

    // prologue: fill FIFO (each slot = 4 timesteps = 2 iterations)
    float4 buf[PD];
#pragma unroll
    for (int j = 0; j < PD; j++) buf[j] = ubase4[j];

    const int NQ = LL / 4;  // 512 float4 chunks
    for (int q0 = 0; q0 < NQ; q0 += PD) {
#pragma unroll
        for (int j = 0; j < PD; j++) {
            int q = q0 + j;
            float4 cur = buf[j];
            int qp = q + PD; if (qp > NQ - 1) qp = NQ - 1;
            buf[j] = ubase4[qp];   // refill (clamped; unused if OOB)

#pragma unroll
            for (int half = 0; half < 2; half++) {
                // iteration parity == half (static): reads [half], writes [1-half]
                float u0 = half ? cur.z : cur.x;
                float u1 = half ? cur.w : cur.y;

                // fence-free reads of OLD T[0] values (written last iteration)
                ull bc56 = smb[half][gl];                       // leader's (S5,S6)old
                ull tb   = (r < 7) ? smb[half][lane + 1] : 0ull; // neighbor old pair0

                // ---- local y (identical in all lanes of the group) ----
                float y0 = fmaf(c0h, u0, S1);
                float y1 = fmaf(A1h, y0, fmaf(c0h, u1, fmaf(C1h, u0, S2)));

                ull y0d = pack2(y0, y0), y1d = pack2(y1, y1);
                ull u0d = pack2(u0, u0), u1d = pack2(u1, u1);

                // ---- head update (local; P34_old / bc56 as bases) ----
                ull nP12 = fma2(HA12o, y1d, fma2(HA12e, y0d,
                            fma2(HC12o, u1d, fma2(HC12e, u0d, P34))));
                ull nP34 = fma2(HA34o, y1d, fma2(HA34e, y0d,
                            fma2(HC34o, u1d, fma2(HC34e, u0d, bc56))));

                // ---- tail update ----
                ull n0 = fma2(Ao[0], y1d, fma2(Ae[0], y0d,
                          fma2(Co[0], u1d, fma2(Ce[0], u0d, T[1]))));
                ull n1 = fma2(Ao[1], y1d, fma2(Ae[1], y0d,
                          fma2(Co[1], u1d, fma2(Ce[1], u0d, T[2]))));
                ull n2 = fma2(Ao[2], y1d, fma2(Ae[2], y0d,
                          fma2(Co[2], u1d, fma2(Ce[2], u0d, T[3]))));
                ull n3 = fma2(Ao[3], y1d, fma2(Ae[3], y0d,
                          fma2(Co[3], u1d, fma2(Ce[3], u0d, tb))));

                // publish fresh T[0] for NEXT iteration (other parity buffer)
                smb[1 - half][lane] = n0;

                T[0] = n0; T[1] = n1; T[2] = n2; T[3] = n3;
                P12 = nP12; P34 = nP34;
                unpack2(P12, S1, S2);

                if (r == 0)
                    ybase2[2 * q + half] = pack2(y0, y1);
            }
        }
    }
}

extern "C" void kernel_launch(void* const* d_in, const int* in_sizes, int n_in,
                              void* d_out, int out_size) {
    const float* u = (const float*)d_in[0];
    const float* k = (const float*)d_in[1];
    if (n_in >= 2 && in_sizes[0] == HH * NN) {  // defensive: swap if order differs
        u = (const float*)d_in[1];
        k = (const float*)d_in[0];
    }
    float* y = (float*)d_out;

    coef_kernel<<<HH, NN>>>(k);
    // 8192 sequences, 4 per warp, one warp per CTA -> 2048 CTAs
    scan_kernel<<<(BB * HH) / 4, 32>>>(u, y);
}

// round 16
// speedup vs baseline: 1.0640x; 1.0640x over previous
#include <cuda_runtime.h>

// StateSpaceDiffusionModel reduced to scalar order-64 IIR+FIR (validated R1+):
//   q_t = sum_{i=0..63} c_i u_{t-i}          (FIR half — Phase A, parallel)
//   y_t = q_t + S1 ; S_i <- S_{i+1} + a'_i y_t  (IIR half — Phase B scan)
// a'_i = a_{i-1}. ISSUE-COUNT MODEL (fits all 14 rounds): duration =
// total_warp_instrs * avg_rt / 592. Split minimizes total instructions:
// FIR standalone at ~85% fma2 density; IIR-only scan with M=4 blocking,
// redundant head (no y-communication), 4 lanes/seq.

#define HH 512
#define NN 64
#define BB 16
#define LL 2048

typedef unsigned long long ull;

__device__ float g_a[HH * NN];
__device__ float g_c[HH * NN];
__device__ ull   g_cd[HH * NN];                    // pre-dupped c taps (c_i, c_i)
__device__ float g_q[(size_t)BB * HH * LL];        // 64 MB FIR scratch

__device__ __forceinline__ ull pack2(float lo, float hi) {
    ull r; asm("mov.b64 %0, {%1,%2};" : "=l"(r) : "f"(lo), "f"(hi)); return r;
}
__device__ __forceinline__ void unpack2(ull v, float& lo, float& hi) {
    asm("mov.b64 {%0,%1}, %2;" : "=f"(lo), "=f"(hi) : "l"(v));
}
__device__ __forceinline__ ull fma2(ull a, ull b, ull c) {
    ull d; asm("fma.rn.f32x2 %0, %1, %2, %3;" : "=l"(d) : "l"(a), "l"(b), "l"(c)); return d;
}

// ---------------- Kernel 1: per-head coefficients (validated) --------------
__global__ void coef_kernel(const float* __restrict__ k) {
    __shared__ float sh[NN];
    __shared__ float shd[NN];
    __shared__ float shP[NN];
    __shared__ float shsum;
    int h = blockIdx.x;
    int j = threadIdx.x;
    float kv = k[h * NN + j];
    float kc = fminf(fmaxf(kv, 1.0f / 16.0f), 1.0f);
    sh[j] = kc;
    __syncthreads();
    if (j == 0) {
        float s = 0.f;
        for (int i = 0; i < NN; i++) s += sh[i];
        shsum = s;
    }
    __syncthreads();
    float kn = kc / shsum;
    float s = (j < NN - 1) ? (1.0f + kn) : kn;
    float w = kn / s;
    shd[j] = 1.0f / s;
    __syncthreads();
    if (j == 0) {
        float P = 1.f;
        for (int i = 0; i < NN; i++) { shP[i] = P; P *= shd[i]; }
    }
    __syncthreads();
    float Pj = shP[j];
    float aj = w * Pj;
    float cj = kv * Pj;
    g_a[h * NN + j] = aj;              // IIR taps: a'_i = g_a[i-1]
    g_c[h * NN + j] = cj;              // FIR taps c_i
    g_cd[h * NN + j] = pack2(cj, cj);  // pre-dupped for fir_kernel
}

// ---------------- Kernel 2 (Phase A): q = c (*) u, 16 outputs/thread -------
// Block = 128 threads = one sequence; thread t0 = 16*tid: outputs q[t0..t0+15].
// Window u[t0-64 .. t0+15] = 80 floats = 20 float4 (aligned; whole-float4 OOB
// zeroing only). Pair accumulation: for tap-pair ii (even i=2ii, odd i=2ii+1):
//   acc_m += cde[ii]*(u_{2m-2ii},u_{2m+1-2ii}) + cdo[ii]*(u_{2m-2ii-1},u_{2m-2ii})
// even-u pairs = natural register pairs of the window; odd-u pairs packed once.
__global__ void __launch_bounds__(128)
fir_kernel(const float* __restrict__ u) {
    int seq = blockIdx.x;
    int h = seq & (HH - 1);
    int tid = threadIdx.x;
    int t0 = tid * 16;
    const float* ub = u + (size_t)seq * LL;
    float* qb = g_q + (size_t)seq * LL;

    // window: uw[j] = u[t0-64+j], j=0..79 (zeros when OOB)
    float4 uw4[20];
#pragma unroll
    for (int kk = 0; kk < 20; kk++) {
        int off = t0 - 64 + 4 * kk;
        uw4[kk] = (off >= 0) ? *(const float4*)(ub + off)
                             : make_float4(0.f, 0.f, 0.f, 0.f);
    }
    const float* uw = (const float*)uw4;
    const ull* ue = (const ull*)uw4;          // ue[p] = (uw[2p], uw[2p+1])

    // odd pairs uo[p] = (uw[2p+1], uw[2p+2]), p = 0..38
    ull uo[39];
#pragma unroll
    for (int p = 0; p < 39; p++) uo[p] = pack2(uw[2 * p + 1], uw[2 * p + 2]);

    ull acc[8];
#pragma unroll
    for (int m = 0; m < 8; m++) acc[m] = 0ull;

    const ull* cd = g_cd + h * NN;
#pragma unroll
    for (int ii = 0; ii < 32; ii++) {
        ull ce = cd[2 * ii];        // dup(c_{2ii})   — adjacent: one LDG.128
        ull co = cd[2 * ii + 1];    // dup(c_{2ii+1})
#pragma unroll
        for (int m = 0; m < 8; m++)
            acc[m] = fma2(ce, ue[m + 32 - ii], fma2(co, uo[m + 31 - ii], acc[m]));
    }

#pragma unroll
    for (int m = 0; m < 8; m++)
        *(ull*)(qb + t0 + 2 * m) = acc[m];
}

// ---------------- Kernel 3 (Phase B): IIR-only M=4 scan, 4 lanes/seq -------
// Warp = 8 sequences x 4 lanes (one warp per CTA, 1024 CTAs).
// AA(m) = a'_m = g_a[m-1] (m<=64 else 0).
// Head slots 1..4 redundant in ALL lanes (y local, zero y-communication):
//   y0 = q0+S1o; y1 = AA1*y0 + (q1+S2o); y2 = AA1*y1+AA2*y0+(q2+S3o);
//   y3 = AA1*y2+AA2*y1+AA3*y0+(q3+S4o)
//   (S1,S2)'''' = (S5o,S6o) + (AA1,AA2)y3d+(AA2,AA3)y2d+(AA3,AA4)y1d+(AA4,AA5)y0d
//   (S3,S4)'''' = (S7o,S8o) + shifted-by-2 taps
// Tail: lane r owns slots 5+16r .. 20+16r as pairs p=0..7 (s = 5+16r+2p):
//   Tp''''[p] = Tp_old[p+2] + (AA(s),AA(s+1))y3d + (AA(s+1),AA(s+2))y2d
//             + (AA(s+2),AA(s+3))y1d + (AA(s+3),AA(s+4))y0d
//   p=6,7 bases = next lane's OLD pairs 0,1 (shfl_down; zero on r==3)
//   head bases (S5..S8)o = group leader's OLD pairs 0,1 (shfl)
// 4 SHFL + 1 LDG.128 + 1 pred-STG.128 per FOUR steps.
__global__ void __launch_bounds__(32)
scan_kernel(const float* __restrict__ q, float* __restrict__ y) {
    int lane = threadIdx.x & 31;
    int g = lane >> 2;    // sequence within warp (0..7)
    int r = lane & 3;     // lane within group (0..3)
    int leader = lane & ~3;
    int seq = blockIdx.x * 8 + g;
    int h = seq & (HH - 1);
    const float4* qb4 = (const float4*)(q + (size_t)seq * LL);
    float4* yb4 = (float4*)(y + (size_t)seq * LL);

    const float* ah = g_a + h * NN;   // AA(m) = ah[m-1], m<=64

#define AA(m) (((m) <= 64) ? ah[(m) - 1] : 0.f)

    // tail taps + state
    ull T3[8], T2[8], T1[8], T0[8], Tp[8];
#pragma unroll
    for (int p = 0; p < 8; p++) {
        int s = 5 + 16 * r + 2 * p;
        float A0v = AA(s), A1v = AA(s + 1), A2v = AA(s + 2), A3v = AA(s + 3), A4v = AA(s + 4);
        T3[p] = pack2(A0v, A1v);
        T2[p] = pack2(A1v, A2v);
        T1[p] = pack2(A2v, A3v);
        T0[p] = pack2(A3v, A4v);
        Tp[p] = 0ull;
    }
    // head taps
    float A1 = AA(1), A2 = AA(2), A3 = AA(3), A4 = AA(4);
    float A5 = AA(5), A6 = AA(6), A7 = AA(7);
    ull H3a = pack2(A1, A2), H2a = pack2(A2, A3), H1a = pack2(A3, A4), H0a = pack2(A4, A5);
    ull H3b = pack2(A3, A4), H2b = pack2(A4, A5), H1b = pack2(A5, A6), H0b = pack2(A6, A7);
    ull P12 = 0ull, P34 = 0ull;
#undef AA

    // q prefetch FIFO (1 float4 = one 4-step iteration)
    float4 buf[2];
    buf[0] = qb4[0];
    buf[1] = qb4[1];

    const int NIT = LL / 4;  // 512 iterations
    for (int n0 = 0; n0 < NIT; n0 += 2) {
#pragma unroll
        for (int j = 0; j < 2; j++) {
            int n = n0 + j;
            float4 cur = buf[j];
            int np = n + 2;
            buf[j] = qb4[np < NIT ? np : NIT - 1];

            // exchanges of OLD state (count: 4 SHFL.64)
            ull hb0 = __shfl_sync(0xffffffffu, Tp[0], leader);   // (S5,S6)o
            ull hb1 = __shfl_sync(0xffffffffu, Tp[1], leader);   // (S7,S8)o
            ull tb0 = __shfl_down_sync(0xffffffffu, Tp[0], 1);
            ull tb1 = __shfl_down_sync(0xffffffffu, Tp[1], 1);
            if (r == 3) { tb0 = 0ull; tb1 = 0ull; }

            // y chain (local in every lane; redundant head)
            float S1o, S2o, S3o, S4o;
            unpack2(P12, S1o, S2o);
            unpack2(P34, S3o, S4o);
            float y0 = cur.x + S1o;
            float y1 = fmaf(A1, y0, cur.y + S2o);
            float y2 = fmaf(A1, y1, fmaf(A2, y0, cur.z + S3o));
            float y3 = fmaf(A1, y2, fmaf(A2, y1, fmaf(A3, y0, cur.w + S4o)));

            ull y0d = pack2(y0, y0), y1d = pack2(y1, y1);
            ull y2d = pack2(y2, y2), y3d = pack2(y3, y3);

            // head update
            P12 = fma2(H3a, y3d, fma2(H2a, y2d, fma2(H1a, y1d, fma2(H0a, y0d, hb0))));
            P34 = fma2(H3b, y3d, fma2(H2b, y2d, fma2(H1b, y1d, fma2(H0b, y0d, hb1))));

            // tail update (bases are OLD pairs; assign after computing all)
            ull n0_ = fma2(T3[0], y3d, fma2(T2[0], y2d, fma2(T1[0], y1d, fma2(T0[0], y0d, Tp[2]))));
            ull n1_ = fma2(T3[1], y3d, fma2(T2[1], y2d, fma2(T1[1], y1d, fma2(T0[1], y0d, Tp[3]))));
            ull n2_ = fma2(T3[2], y3d, fma2(T2[2], y2d, fma2(T1[2], y1d, fma2(T0[2], y0d, Tp[4]))));
            ull n3_ = fma2(T3[3], y3d, fma2(T2[3], y2d, fma2(T1[3], y1d, fma2(T0[3], y0d, Tp[5]))));
            ull n4_ = fma2(T3[4], y3d, fma2(T2[4], y2d, fma2(T1[4], y1d, fma2(T0[4], y0d, Tp[6]))));
            ull n5_ = fma2(T3[5], y3d, fma2(T2[5], y2d, fma2(T1[5], y1d, fma2(T0[5], y0d, Tp[7]))));
            ull n6_ = fma2(T3[6], y3d, fma2(T2[6], y2d, fma2(T1[6], y1d, fma2(T0[6], y0d, tb0))));
            ull n7_ = fma2(T3[7], y3d, fma2(T2[7], y2d, fma2(T1[7], y1d, fma2(T0[7], y0d, tb1))));
            Tp[0] = n0_; Tp[1] = n1_; Tp[2] = n2_; Tp[3] = n3_;
            Tp[4] = n4_; Tp[5] = n5_; Tp[6] = n6_; Tp[7] = n7_;

            if (r == 0)
                yb4[n] = make_float4(y0, y1, y2, y3);
        }
    }
}

extern "C" void kernel_launch(void* const* d_in, const int* in_sizes, int n_in,
                              void* d_out, int out_size) {
    const float* u = (const float*)d_in[0];
    const float* k = (const float*)d_in[1];
    if (n_in >= 2 && in_sizes[0] == HH * NN) {  // defensive: swap if order differs
        u = (const float*)d_in[1];
        k = (const float*)d_in[0];
    }
    float* y = (float*)d_out;

    coef_kernel<<<HH, NN>>>(k);
    // Phase A: FIR q = c (*) u. One 128-thread block per sequence.
    fir_kernel<<<BB * HH, 128>>>(u);
    // Phase B: IIR-only scan. 8 seqs/warp, one warp per CTA.
    float* qptr;
    cudaGetSymbolAddress((void**)&qptr, g_q);
    scan_kernel<<<(BB * HH) / 8, 32>>>(qptr, y);
}

// round 17
// speedup vs baseline: 1.4810x; 1.3919x over previous
#include <cuda_runtime.h>

// StateSpaceDiffusionModel: y[b,h,:] = causal_conv(u[b,h,:], f[h,:])
// reduced exactly to a scalar order-64 IIR+FIR (transposed direct form II):
//   y_t = c0*u_t + S[1]
//   S[i] <- S[i+1] + A'[i]*y_t + C'[i]*u_t   (merged delay line, i=1..64)
// A'[i] = a_{i-1} (1<=i<=64), C'[i] = c_i (1<=i<=63).
//
// R16 = champion R3 body with SWAP-PACK multiplicands: taps re-paired so the
// fma2 multiplicands are registers that already exist -- Y01 = broadcast ypk
// (free), U01 = (u0,u1) float4 sub-pair (free), plus swapped Y10/U10 (4 MOV).
// Removes the 4 duplicate packs + unpack (10 MOV32 -> 4 MOV32 per iteration).
// Same 16 fma2, same tap register count, same launch/layout as champion.

#define HH 512
#define NN 64
#define BB 16
#define LL 2048

__device__ float g_a[HH * NN];
__device__ float g_c[HH * NN];

// ---------------- Kernel 1: per-head coefficients (trivial) ----------------
__global__ void coef_kernel(const float* __restrict__ k) {
    __shared__ float sh[NN];
    __shared__ float shd[NN];
    __shared__ float shP[NN];
    __shared__ float shsum;
    int h = blockIdx.x;
    int j = threadIdx.x;
    float kv = k[h * NN + j];
    float kc = fminf(fmaxf(kv, 1.0f / 16.0f), 1.0f);
    sh[j] = kc;
    __syncthreads();
    if (j == 0) {
        float s = 0.f;
        for (int i = 0; i < NN; i++) s += sh[i];
        shsum = s;
    }
    __syncthreads();
    float kn = kc / shsum;                       // L1-normalized clamped k
    float s = (j < NN - 1) ? (1.0f + kn) : kn;   // column L1 norm of (A + b k^T)
    float w = kn / s;                            // M[0, j]
    shd[j] = 1.0f / s;                           // M[j+1, j] subdiagonal
    __syncthreads();
    if (j == 0) {
        float P = 1.f;
        for (int i = 0; i < NN; i++) { shP[i] = P; P *= shd[i]; }
    }
    __syncthreads();
    float Pj = shP[j];
    g_a[h * NN + j] = w * Pj;    // IIR taps
    g_c[h * NN + j] = kv * Pj;   // FIR taps (original k!)
}

// ---------------- packed f32x2 helpers ----------------
typedef unsigned long long ull;
__device__ __forceinline__ ull pack2(float lo, float hi) {
    ull r; asm("mov.b64 %0, {%1,%2};" : "=l"(r) : "f"(lo), "f"(hi)); return r;
}
__device__ __forceinline__ void unpack2(ull v, float& lo, float& hi) {
    asm("mov.b64 {%0,%1}, %2;" : "=f"(lo), "=f"(hi) : "l"(v));
}
__device__ __forceinline__ ull fma2(ull a, ull b, ull c) {
    ull d; asm("fma.rn.f32x2 %0, %1, %2, %3;" : "=l"(d) : "l"(a), "l"(b), "l"(c)); return d;
}

// ---------------- Kernel 2: fused scan, swap-pack multiplicands ------------
// Two timesteps per iteration. pair p = slots (2p+1, 2p+2), p = 0..31.
// Per pair, with s = 2p+1 (lo slot):
//   [lo,hi]'' = dup(A'(s+1))*(y0,y1) + (A'(s),A'(s+2))*(y1,y0)
//             + dup(C'(s+1))*(u0,u1) + (C'(s),C'(s+2))*(u1,u0) + base
// Warp = 4 sequences x 8 lanes; lane r owns pairs 4r..4r+3 (slots 8r+1..8r+8).
// u read as float4 (2 iterations per load) through a 4-slot register FIFO;
// y written as float4 every 2 iterations.
#define PD2 4   // float4 FIFO slots; each slot feeds 2 iterations (4 timesteps)

__global__ void __launch_bounds__(128, 4)
scan_kernel(const float* __restrict__ u, float* __restrict__ y) {
    int warp = blockIdx.x * (blockDim.x >> 5) + (threadIdx.x >> 5);
    int lane = threadIdx.x & 31;
    int g = lane >> 3;   // sequence within warp (0..3)
    int r = lane & 7;    // lane within group (0..7)
    int leader = lane & ~7;
    int seq = warp * 4 + g;           // 0..8191
    int h = seq & (HH - 1);
    const float4* ubase4 = (const float4*)(u + (size_t)seq * LL);
    float4* ybase4 = (float4*)(y + (size_t)seq * LL);

    const float* ah = g_a + h * NN;
    const float* ch = g_c + h * NN;

    // taps re-paired for swap-pack multiplicands
    ull AeD[4], Ax[4], CeD[4], Cx[4], S[4];
#pragma unroll
    for (int i = 0; i < 4; i++) {
        int p = r * 4 + i;
        int i1 = 2 * p + 1, i2 = 2 * p + 2, i3 = 2 * p + 3;   // s, s+1, s+2
        // A'[idx] = a[idx-1] for 1<=idx<=64 ; C'[idx] = c[idx] for 1<=idx<=63
        float A1 = (i1 <= 64) ? ah[i1 - 1] : 0.f;
        float A2 = (i2 <= 64) ? ah[i2 - 1] : 0.f;
        float A3 = (i3 <= 64) ? ah[i3 - 1] : 0.f;
        float C1 = (i1 <= 63) ? ch[i1] : 0.f;
        float C2 = (i2 <= 63) ? ch[i2] : 0.f;
        float C3 = (i3 <= 63) ? ch[i3] : 0.f;
        AeD[i] = pack2(A2, A2);   // * (y0,y1)
        Ax[i]  = pack2(A1, A3);   // * (y1,y0)
        CeD[i] = pack2(C2, C2);   // * (u0,u1)
        Cx[i]  = pack2(C1, C3);   // * (u1,u0)
        S[i] = 0ull;
    }
    float c0h = ch[0], c1h = ch[1], a0h = ah[0];
    float SS1 = 0.f, SS2 = 0.f;   // unpacked old S[0] (valid on r==0)

    // prologue: fill FIFO (each slot covers 4 timesteps)
    float4 buf[PD2];
#pragma unroll
    for (int j = 0; j < PD2; j++)
        buf[j] = ubase4[j];

    const int NQ = LL / 4;  // 512 four-step chunks
    for (int q0 = 0; q0 < NQ; q0 += PD2) {
#pragma unroll
        for (int j = 0; j < PD2; j++) {
            int q = q0 + j;             // chunk index: timesteps 4q..4q+3
            float4 cur = buf[j];
            int qp = q + PD2;
            if (qp > NQ - 1) qp = NQ - 1;   // clamped refill (unused if OOB)
            buf[j] = ubase4[qp];

            float2 yout01, yout23;
            // ---- iteration A: timesteps 4q, 4q+1 (u = cur.x, cur.y) ----
            {
                ull sn = __shfl_down_sync(0xffffffffu, S[0], 1);
                if (r == 7) sn = 0ull;
                float u0 = cur.x, u1 = cur.y;
                float y0 = fmaf(c0h, u0, SS1);
                float y1 = fmaf(a0h, y0, fmaf(c1h, u0, fmaf(c0h, u1, SS2)));
                ull ypk = __shfl_sync(0xffffffffu, pack2(y0, y1), leader);  // Y01
                float y0b, y1b; unpack2(ypk, y0b, y1b);
                ull Y10 = pack2(y1b, y0b);
                ull U01 = pack2(u0, u1);          // aligned float4 sub-pair
                ull U10 = pack2(u1, u0);
#pragma unroll
                for (int i = 0; i < 3; i++)
                    S[i] = fma2(AeD[i], ypk, fma2(Ax[i], Y10,
                            fma2(CeD[i], U01, fma2(Cx[i], U10, S[i + 1]))));
                S[3] = fma2(AeD[3], ypk, fma2(Ax[3], Y10,
                         fma2(CeD[3], U01, fma2(Cx[3], U10, sn))));
                unpack2(S[0], SS1, SS2);
                yout01 = make_float2(y0, y1);
            }
            // ---- iteration B: timesteps 4q+2, 4q+3 (u = cur.z, cur.w) ----
            {
                ull sn = __shfl_down_sync(0xffffffffu, S[0], 1);
                if (r == 7) sn = 0ull;
                float u0 = cur.z, u1 = cur.w;
                float y0 = fmaf(c0h, u0, SS1);
                float y1 = fmaf(a0h, y0, fmaf(c1h, u0, fmaf(c0h, u1, SS2)));
                ull ypk = __shfl_sync(0xffffffffu, pack2(y0, y1), leader);  // Y01
                float y0b, y1b; unpack2(ypk, y0b, y1b);
                ull Y10 = pack2(y1b, y0b);
                ull U01 = pack2(u0, u1);
                ull U10 = pack2(u1, u0);
#pragma unroll
                for (int i = 0; i < 3; i++)
                    S[i] = fma2(AeD[i], ypk, fma2(Ax[i], Y10,
                            fma2(CeD[i], U01, fma2(Cx[i], U10, S[i + 1]))));
                S[3] = fma2(AeD[3], ypk, fma2(Ax[3], Y10,
                         fma2(CeD[3], U01, fma2(Cx[3], U10, sn))));
                unpack2(S[0], SS1, SS2);
                yout23 = make_float2(y0, y1);
            }

            if (r == 0)
                ybase4[q] = make_float4(yout01.x, yout01.y, yout23.x, yout23.y);
        }
    }
}

extern "C" void kernel_launch(void* const* d_in, const int* in_sizes, int n_in,
                              void* d_out, int out_size) {
    const float* u = (const float*)d_in[0];
    const float* k = (const float*)d_in[1];
    if (n_in >= 2 && in_sizes[0] == HH * NN) {  // defensive: swap if order differs
        u = (const float*)d_in[1];
        k = (const float*)d_in[0];
    }
    float* y = (float*)d_out;

    coef_kernel<<<HH, NN>>>(k);
    // 8192 sequences, 4 per warp, 4 warps per 128-thread CTA -> 512 CTAs
    scan_kernel<<<(BB * HH) / 16, 128>>>(u, y);
}